// round 16
// baseline (speedup 1.0000x reference)
#include <cuda_runtime.h>
#include <cuda_bf16.h>
#include <cuda_fp16.h>

#define NN 50000
#define EE 800000
#define HD 128            // H*D
#define IN_DIM 256
#define NEG_SLOPE 0.2f
#define BN_EPS 1e-5f
#define NB 196            // ceil(NN/256) scan blocks

// ---------------- scratch (device globals; zero-initialized at load) ---------
// g_cnt is re-zeroed each call by bn_apply (for the next replay); g_sums/
// g_sumsq are zeroed by scan_fused before agg accumulates them.
__device__ __half   g_hh[NN * HD];      // projected features fp16 [N,128]
__device__ float    g_el[NN * 4];       // attn-left  per node per head (fp32)
__device__ float    g_er[NN * 4];       // attn-right per node per head (fp32)
__device__ unsigned g_cnt[NN];          // in-degree histogram
__device__ unsigned g_off[NN + 1];      // CSR offsets (by dst)
__device__ unsigned g_bsum[NB];         // per-block count sums
__device__ int      g_rank[EE];         // edge rank within its dst segment
__device__ int      g_esrc[EE];         // src node id per CSR slot
__device__ float    g_rst[NN * HD];     // aggregated messages (fp32)
__device__ float    g_sums[HD];
__device__ float    g_sumsq[HD];

__device__ __forceinline__ float sel4(float4 v, int i) {
    float r = v.x;
    if (i == 1) r = v.y; else if (i == 2) r = v.z; else if (i == 3) r = v.w;
    return r;
}

__device__ __forceinline__ unsigned f2tf32(float f) {
    unsigned u;
    asm("cvt.rna.tf32.f32 %0, %1;" : "=r"(u) : "f"(f));
    return u;
}

__device__ __forceinline__ void mma_tf32(float4& c, const unsigned a[4],
                                         unsigned b0, unsigned b1) {
    asm volatile(
        "mma.sync.aligned.m16n8k8.row.col.f32.tf32.tf32.f32 "
        "{%0,%1,%2,%3}, {%4,%5,%6,%7}, {%8,%9}, {%0,%1,%2,%3};"
        : "+f"(c.x), "+f"(c.y), "+f"(c.z), "+f"(c.w)
        : "r"(a[0]), "r"(a[1]), "r"(a[2]), "r"(a[3]), "r"(b0), "r"(b1));
}

__device__ __forceinline__ void cp_async16(unsigned saddr, const void* gaddr,
                                           int src_bytes) {
    asm volatile("cp.async.cg.shared.global [%0], [%1], 16, %2;"
                 :: "r"(saddr), "l"(gaddr), "r"(src_bytes));
}

// ---------------- CSR build: histogram + per-edge rank (scalar, R14) ---------
__global__ void hist_kernel(const int* __restrict__ dst) {
    int e = blockIdx.x * blockDim.x + threadIdx.x;
    if (e < EE) g_rank[e] = (int)atomicAdd(&g_cnt[dst[e]], 1u);
}

// ---------------- CSR build: per-block scan ----------------------------------
__global__ void scan_block_kernel() {
    __shared__ unsigned sh[256];
    int t = threadIdx.x;
    int idx = blockIdx.x * 256 + t;
    unsigned v = (idx < NN) ? g_cnt[idx] : 0u;
    sh[t] = v;
    __syncthreads();
#pragma unroll
    for (int off = 1; off < 256; off <<= 1) {
        unsigned p = (t >= off) ? sh[t - off] : 0u;
        __syncthreads();
        sh[t] += p;
        __syncthreads();
    }
    if (idx < NN) g_off[idx] = sh[t] - v;            // local exclusive
    if (t == 255) g_bsum[blockIdx.x] = sh[255];
}

// ---------------- CSR build: fused top-scan + add-back -----------------------
__global__ void scan_fused_kernel() {
    __shared__ unsigned red[256];
    const int b = blockIdx.x, t = threadIdx.x;
    red[t] = (t < b) ? g_bsum[t] : 0u;               // b <= 195 < 256
    __syncthreads();
#pragma unroll
    for (int off = 128; off > 0; off >>= 1) {
        if (t < off) red[t] += red[t + off];
        __syncthreads();
    }
    const unsigned bpre = red[0];
    int idx = b * 256 + t;
    if (idx < NN) g_off[idx] += bpre;
    if (b == 0) {
        if (t == 0) g_off[NN] = EE;
        if (t < HD) { g_sums[t] = 0.f; g_sumsq[t] = 0.f; }
    }
}

// ---------------- CSR build: atomic-free scatter (scalar, R14; slot #4) ------
__global__ void scatter_kernel(const int* __restrict__ src,
                               const int* __restrict__ dst) {
    int e = blockIdx.x * blockDim.x + threadIdx.x;
    if (e >= EE) return;
    int d = dst[e];
    g_esrc[g_off[d] + g_rank[e]] = src[e];
}

// ---------------- GEMM h = x@W via tf32 mma + cp.async double-buffer ---------
// R10/R12-proven: 2-stage LDGSTS ring, wait_group 1. Block tile 128x128, K16.
#define SA2 20    // As row stride (floats): banks (20r+c)%32 conflict-free
#define SB2 136   // Bs row stride (floats)
#define ATF (128 * SA2)   // floats per A stage
#define BTF (16 * SB2)    // floats per B stage
__global__ void __launch_bounds__(256, 2) gemm_kernel(
    const float* __restrict__ x, const float* __restrict__ W,
    const float* __restrict__ attn_l, const float* __restrict__ attn_r)
{
    __shared__ float As[2 * ATF];
    __shared__ float Bs[2 * BTF];
    const int tid  = threadIdx.x;
    const int warp = tid >> 5, lane = tid & 31;
    const int wr = warp >> 2, wc = warp & 3;
    const int gid = lane >> 2, tig = lane & 3;
    const int row0 = blockIdx.x * 128;

    const unsigned as_b = (unsigned)__cvta_generic_to_shared(As);
    const unsigned bs_b = (unsigned)__cvta_generic_to_shared(Bs);

    const int ac0 = tid, ac1 = tid + 256;
    const int ar0 = ac0 >> 2, ao0 = (ac0 & 3) * 4;
    const int ar1 = ac1 >> 2, ao1 = (ac1 & 3) * 4;
    const int g0 = row0 + ar0, g1 = row0 + ar1;
    const int av0 = (g0 < NN) ? 16 : 0, av1 = (g1 < NN) ? 16 : 0;
    const float* ap0 = x + (long)((g0 < NN) ? g0 : 0) * IN_DIM + ao0;
    const float* ap1 = x + (long)((g1 < NN) ? g1 : 0) * IN_DIM + ao1;
    const int br0 = ac0 >> 5, bo0 = (ac0 & 31) * 4;
    const int br1 = ac1 >> 5, bo1 = (ac1 & 31) * 4;
    const float* bp0 = W + br0 * HD + bo0;
    const float* bp1 = W + br1 * HD + bo1;

    auto load_tile = [&](int k0, int s) {
        unsigned ab = as_b + 4u * (s * ATF);
        unsigned bb = bs_b + 4u * (s * BTF);
        cp_async16(ab + 4u * (ar0 * SA2 + ao0), ap0 + k0, av0);
        cp_async16(ab + 4u * (ar1 * SA2 + ao1), ap1 + k0, av1);
        cp_async16(bb + 4u * (br0 * SB2 + bo0), bp0 + (long)k0 * HD, 16);
        cp_async16(bb + 4u * (br1 * SB2 + bo1), bp1 + (long)k0 * HD, 16);
        asm volatile("cp.async.commit_group;");
    };

    float4 c[4][4];
#pragma unroll
    for (int mt = 0; mt < 4; mt++)
#pragma unroll
        for (int nt = 0; nt < 4; nt++) c[mt][nt] = make_float4(0.f, 0.f, 0.f, 0.f);

    load_tile(0, 0);

    const int NT = IN_DIM / 16;    // 16 tiles
    for (int t = 0; t < NT; t++) {
        if (t + 1 < NT) {
            load_tile((t + 1) * 16, (t + 1) & 1);
            asm volatile("cp.async.wait_group 1;");
        } else {
            asm volatile("cp.async.wait_group 0;");
        }
        __syncthreads();

        const float* Af = As + (t & 1) * ATF;
        const float* Bf = Bs + (t & 1) * BTF;
#pragma unroll
        for (int kk = 0; kk < 2; kk++) {
            unsigned a[4][4], b[4][2];
            const int kb = kk * 8 + tig;
#pragma unroll
            for (int mt = 0; mt < 4; mt++) {
                int row = wr * 64 + mt * 16 + gid;
                a[mt][0] = f2tf32(Af[row * SA2 + kb]);
                a[mt][1] = f2tf32(Af[(row + 8) * SA2 + kb]);
                a[mt][2] = f2tf32(Af[row * SA2 + kb + 4]);
                a[mt][3] = f2tf32(Af[(row + 8) * SA2 + kb + 4]);
            }
#pragma unroll
            for (int nt = 0; nt < 4; nt++) {
                int col = wc * 32 + nt * 8 + gid;
                b[nt][0] = f2tf32(Bf[kb * SB2 + col]);
                b[nt][1] = f2tf32(Bf[(kb + 4) * SB2 + col]);
            }
#pragma unroll
            for (int mt = 0; mt < 4; mt++)
#pragma unroll
                for (int nt = 0; nt < 4; nt++)
                    mma_tf32(c[mt][nt], a[mt], b[nt][0], b[nt][1]);
        }
        __syncthreads();   // stage (t&1) free for tile t+2's loads
    }

    // ---- epilogue: store h (fp16), reduce el/er fp32 (warp-col wc == head) --
    const int head = wc;
    float al[4][2], arr[4][2];
#pragma unroll
    for (int nt = 0; nt < 4; nt++) {
        int col = wc * 32 + nt * 8 + 2 * tig;
        al[nt][0] = attn_l[col];     al[nt][1] = attn_l[col + 1];
        arr[nt][0] = attn_r[col];    arr[nt][1] = attn_r[col + 1];
    }

#pragma unroll
    for (int mt = 0; mt < 4; mt++) {
        int r0 = row0 + wr * 64 + mt * 16 + gid;     // and r0+8
        float pl0 = 0.f, pr0 = 0.f, pl1 = 0.f, pr1 = 0.f;
#pragma unroll
        for (int nt = 0; nt < 4; nt++) {
            float4 v = c[mt][nt];
            pl0 = fmaf(v.x, al[nt][0], fmaf(v.y, al[nt][1], pl0));
            pr0 = fmaf(v.x, arr[nt][0], fmaf(v.y, arr[nt][1], pr0));
            pl1 = fmaf(v.z, al[nt][0], fmaf(v.w, al[nt][1], pl1));
            pr1 = fmaf(v.z, arr[nt][0], fmaf(v.w, arr[nt][1], pr1));
        }
#pragma unroll
        for (int o = 1; o <= 2; o <<= 1) {
            pl0 += __shfl_xor_sync(0xffffffffu, pl0, o);
            pr0 += __shfl_xor_sync(0xffffffffu, pr0, o);
            pl1 += __shfl_xor_sync(0xffffffffu, pl1, o);
            pr1 += __shfl_xor_sync(0xffffffffu, pr1, o);
        }
        if (tig == 0) {
            if (r0 < NN)     { g_el[r0 * 4 + head] = pl0;       g_er[r0 * 4 + head] = pr0; }
            if (r0 + 8 < NN) { g_el[(r0 + 8) * 4 + head] = pl1; g_er[(r0 + 8) * 4 + head] = pr1; }
        }
#pragma unroll
        for (int nt = 0; nt < 4; nt++) {
            int col = wc * 32 + nt * 8 + 2 * tig;
            float4 v = c[mt][nt];
            if (r0 < NN)
                *(__half2*)&g_hh[r0 * HD + col]       = __floats2half2_rn(v.x, v.y);
            if (r0 + 8 < NN)
                *(__half2*)&g_hh[(r0 + 8) * HD + col] = __floats2half2_rn(v.z, v.w);
        }
    }
}

// ---------------- fused softmax + aggregation + BN stats ---------------------
// R14's warp-per-node agg (50k warps, unchanged scheduling; grid is exactly
// 6250 blocks x 8 warps = 50000 nodes, no tail) + block-level BN reduction:
// lane l owns channels 4l..4l+3, so (o, o^2) partials reduce through smem and
// 8 atomics per lane of warp 0 — deletes the bn_stats kernel entirely.
__global__ void __launch_bounds__(256) agg_kernel() {
    const int gwarp = (blockIdx.x * 256 + threadIdx.x) >> 5;
    const int warp = threadIdx.x >> 5;
    const int l = threadIdx.x & 31;
    const int hh = l >> 3;                 // 8 lanes per head
    const uint2* hmat = (const uint2*)g_hh;   // row = 32 uint2 (128 halves)

    float4 o = make_float4(0.f, 0.f, 0.f, 0.f);
    const int d = gwarp;                      // always < NN (exact grid)
    {
        const int beg = (int)g_off[d], end = (int)g_off[d + 1];
        const float4 er4 = ((const float4*)g_er)[d];
        const float erc = sel4(er4, hh);

        float4 acc = make_float4(0.f, 0.f, 0.f, 0.f);
        float sumex = 0.f;

        int i = beg;
        for (; i + 1 < end; i += 2) {
            int s0 = __ldg(&g_esrc[i]);
            int s1 = __ldg(&g_esrc[i + 1]);
            float4 el0 = ((const float4*)g_el)[s0];
            float4 el1 = ((const float4*)g_el)[s1];
            uint2 u0 = hmat[s0 * 32 + l];
            uint2 u1 = hmat[s1 * 32 + l];

            float e0 = sel4(el0, hh) + erc;
            e0 = e0 > 0.f ? e0 : NEG_SLOPE * e0;
            float ex0 = __expf(e0);
            float e1 = sel4(el1, hh) + erc;
            e1 = e1 > 0.f ? e1 : NEG_SLOPE * e1;
            float ex1 = __expf(e1);
            sumex += ex0 + ex1;

            float2 a01 = __half22float2(*(__half2*)&u0.x);
            float2 a23 = __half22float2(*(__half2*)&u0.y);
            float2 b01 = __half22float2(*(__half2*)&u1.x);
            float2 b23 = __half22float2(*(__half2*)&u1.y);
            acc.x = fmaf(ex0, a01.x, fmaf(ex1, b01.x, acc.x));
            acc.y = fmaf(ex0, a01.y, fmaf(ex1, b01.y, acc.y));
            acc.z = fmaf(ex0, a23.x, fmaf(ex1, b23.x, acc.z));
            acc.w = fmaf(ex0, a23.y, fmaf(ex1, b23.y, acc.w));
        }
        if (i < end) {
            int s = __ldg(&g_esrc[i]);
            float4 el4 = ((const float4*)g_el)[s];
            uint2 u0 = hmat[s * 32 + l];
            float e = sel4(el4, hh) + erc;
            e = e > 0.f ? e : NEG_SLOPE * e;
            float ex = __expf(e);
            sumex += ex;
            float2 a01 = __half22float2(*(__half2*)&u0.x);
            float2 a23 = __half22float2(*(__half2*)&u0.y);
            acc.x = fmaf(ex, a01.x, acc.x);
            acc.y = fmaf(ex, a01.y, acc.y);
            acc.z = fmaf(ex, a23.x, acc.z);
            acc.w = fmaf(ex, a23.y, acc.w);
        }
        float inv = (sumex > 0.f) ? 1.f / sumex : 0.f;
        o.x = acc.x * inv; o.y = acc.y * inv;
        o.z = acc.z * inv; o.w = acc.w * inv;
        ((float4*)g_rst)[d * 32 + l] = o;
    }

    // ---- BN stats: block reduction over the 8 warps' node outputs ----
    __shared__ float4 ssum[8][32], ssq[8][32];
    float4 sq;
    sq.x = o.x * o.x; sq.y = o.y * o.y;
    sq.z = o.z * o.z; sq.w = o.w * o.w;
    ssum[warp][l] = o;  ssq[warp][l] = sq;
    __syncthreads();
    if (warp == 0) {
        float4 s = ssum[0][l], s2 = ssq[0][l];
#pragma unroll
        for (int w = 1; w < 8; w++) {
            float4 a = ssum[w][l], a2 = ssq[w][l];
            s.x += a.x; s.y += a.y; s.z += a.z; s.w += a.w;
            s2.x += a2.x; s2.y += a2.y; s2.z += a2.z; s2.w += a2.w;
        }
        atomicAdd(&g_sums[4 * l + 0], s.x);
        atomicAdd(&g_sums[4 * l + 1], s.y);
        atomicAdd(&g_sums[4 * l + 2], s.z);
        atomicAdd(&g_sums[4 * l + 3], s.w);
        atomicAdd(&g_sumsq[4 * l + 0], s2.x);
        atomicAdd(&g_sumsq[4 * l + 1], s2.y);
        atomicAdd(&g_sumsq[4 * l + 2], s2.z);
        atomicAdd(&g_sumsq[4 * l + 3], s2.w);
    }
}

// ---------------- BN normalize + ReLU + next-replay cleanup ------------------
__global__ void bn_apply_kernel(const float* __restrict__ gamma,
                                const float* __restrict__ beta,
                                float* __restrict__ out)
{
    int i = blockIdx.x * blockDim.x + threadIdx.x;   // NN*HD/4 threads
    int c0 = (i * 4) & (HD - 1);
    const float inv_n = 1.f / (float)NN;
    float4 v = ((const float4*)g_rst)[i];
    float4 o;
#pragma unroll
    for (int j = 0; j < 4; j++) {
        int c = c0 + j;
        float mean = g_sums[c] * inv_n;
        float var  = g_sumsq[c] * inv_n - mean * mean;
        float vv = (j == 0) ? v.x : (j == 1) ? v.y : (j == 2) ? v.z : v.w;
        float y = gamma[c] * (vv - mean) * rsqrtf(var + BN_EPS) + beta[c];
        y = y > 0.f ? y : 0.f;
        if (j == 0) o.x = y; else if (j == 1) o.y = y;
        else if (j == 2) o.z = y; else o.w = y;
    }
    ((float4*)out)[i] = o;
    // reset g_cnt for the next replay (g_cnt's last read was launch 2)
    if (i < NN) g_cnt[i] = 0u;
}

// ---------------- launch -----------------------------------------------------
// 7 launches. scatter_kernel at profiled slot #4 (R14 scalar version).
extern "C" void kernel_launch(void* const* d_in, const int* in_sizes, int n_in,
                              void* d_out, int out_size)
{
    const float* x      = (const float*)d_in[0];
    const int*   src    = (const int*)d_in[1];
    const int*   dst    = (const int*)d_in[2];
    const float* W      = (const float*)d_in[3];
    const float* attn_l = (const float*)d_in[4];
    const float* attn_r = (const float*)d_in[5];
    // d_in[6] = bias: constant per-channel shift, cancels inside batch-norm
    const float* gamma  = (const float*)d_in[7];
    const float* beta   = (const float*)d_in[8];
    float* out = (float*)d_out;

    hist_kernel<<<(EE + 255) / 256, 256>>>(dst);
    scan_block_kernel<<<NB, 256>>>();
    scan_fused_kernel<<<NB, 256>>>();
    scatter_kernel<<<(EE + 255) / 256, 256>>>(src, dst);   // profiled
    gemm_kernel<<<(NN + 127) / 128, 256>>>(x, W, attn_l, attn_r);
    agg_kernel<<<(NN * 32) / 256, 256>>>();                // exact: 6250 blocks
    bn_apply_kernel<<<(NN * HD / 4 + 255) / 256, 256>>>(gamma, beta, out);
}

// round 17
// speedup vs baseline: 1.5977x; 1.5977x over previous
#include <cuda_runtime.h>
#include <cuda_bf16.h>
#include <cuda_fp16.h>

#define NN 50000
#define EE 800000
#define HD 128            // H*D
#define IN_DIM 256
#define NEG_SLOPE 0.2f
#define BN_EPS 1e-5f
#define NB 196            // ceil(NN/256) scan blocks

// ---------------- scratch (device globals; zero-initialized at load) ---------
// g_cnt is re-zeroed each call by bn_apply (for the next replay); g_sums/
// g_sumsq are zeroed by scan_fused before bn_stats accumulates.
__device__ __half   g_hh[NN * HD];      // projected features fp16 [N,128]
__device__ float    g_el[NN * 4];       // attn-left  per node per head (fp32)
__device__ float    g_er[NN * 4];       // attn-right per node per head (fp32)
__device__ unsigned g_cnt[NN];          // in-degree histogram
__device__ unsigned g_off[NN + 1];      // CSR offsets (by dst)
__device__ unsigned g_bsum[NB];         // per-block count sums
__device__ int      g_rank[EE];         // edge rank within its dst segment
__device__ int      g_esrc[EE];         // src node id per CSR slot
__device__ float    g_rst[NN * HD];     // aggregated messages (fp32)
__device__ float    g_sums[HD];
__device__ float    g_sumsq[HD];

__device__ __forceinline__ float sel4(float4 v, int i) {
    float r = v.x;
    if (i == 1) r = v.y; else if (i == 2) r = v.z; else if (i == 3) r = v.w;
    return r;
}

__device__ __forceinline__ unsigned f2tf32(float f) {
    unsigned u;
    asm("cvt.rna.tf32.f32 %0, %1;" : "=r"(u) : "f"(f));
    return u;
}

__device__ __forceinline__ void mma_tf32(float4& c, const unsigned a[4],
                                         unsigned b0, unsigned b1) {
    asm volatile(
        "mma.sync.aligned.m16n8k8.row.col.f32.tf32.tf32.f32 "
        "{%0,%1,%2,%3}, {%4,%5,%6,%7}, {%8,%9}, {%0,%1,%2,%3};"
        : "+f"(c.x), "+f"(c.y), "+f"(c.z), "+f"(c.w)
        : "r"(a[0]), "r"(a[1]), "r"(a[2]), "r"(a[3]), "r"(b0), "r"(b1));
}

__device__ __forceinline__ void cp_async16(unsigned saddr, const void* gaddr,
                                           int src_bytes) {
    asm volatile("cp.async.cg.shared.global [%0], [%1], 16, %2;"
                 :: "r"(saddr), "l"(gaddr), "r"(src_bytes));
}

// ---------------- CSR build: histogram + per-edge rank -----------------------
__global__ void hist_kernel(const int* __restrict__ dst) {
    int e = blockIdx.x * blockDim.x + threadIdx.x;
    if (e < EE) g_rank[e] = (int)atomicAdd(&g_cnt[dst[e]], 1u);
}

// ---------------- CSR build: per-block scan ----------------------------------
__global__ void scan_block_kernel() {
    __shared__ unsigned sh[256];
    int t = threadIdx.x;
    int idx = blockIdx.x * 256 + t;
    unsigned v = (idx < NN) ? g_cnt[idx] : 0u;
    sh[t] = v;
    __syncthreads();
#pragma unroll
    for (int off = 1; off < 256; off <<= 1) {
        unsigned p = (t >= off) ? sh[t - off] : 0u;
        __syncthreads();
        sh[t] += p;
        __syncthreads();
    }
    if (idx < NN) g_off[idx] = sh[t] - v;            // local exclusive
    if (t == 255) g_bsum[blockIdx.x] = sh[255];
}

// ---------------- CSR build: fused top-scan + add-back -----------------------
__global__ void scan_fused_kernel() {
    __shared__ unsigned red[256];
    const int b = blockIdx.x, t = threadIdx.x;
    red[t] = (t < b) ? g_bsum[t] : 0u;               // b <= 195 < 256
    __syncthreads();
#pragma unroll
    for (int off = 128; off > 0; off >>= 1) {
        if (t < off) red[t] += red[t + off];
        __syncthreads();
    }
    const unsigned bpre = red[0];
    int idx = b * 256 + t;
    if (idx < NN) g_off[idx] += bpre;
    if (b == 0) {
        if (t == 0) g_off[NN] = EE;
        if (t < HD) { g_sums[t] = 0.f; g_sumsq[t] = 0.f; }
    }
}

// ---------------- CSR build: atomic-free scatter (profiled slot #4) ----------
__global__ void scatter_kernel(const int* __restrict__ src,
                               const int* __restrict__ dst) {
    int e = blockIdx.x * blockDim.x + threadIdx.x;
    if (e >= EE) return;
    int d = dst[e];
    g_esrc[g_off[d] + g_rank[e]] = src[e];
}

// ---------------- GEMM h = x@W via tf32 mma + cp.async double-buffer ---------
// R10/R12-proven: 2-stage LDGSTS ring, wait_group 1. Block tile 128x128, K16.
#define SA2 20    // As row stride (floats): banks (20r+c)%32 conflict-free
#define SB2 136   // Bs row stride (floats)
#define ATF (128 * SA2)   // floats per A stage
#define BTF (16 * SB2)    // floats per B stage
__global__ void __launch_bounds__(256, 2) gemm_kernel(
    const float* __restrict__ x, const float* __restrict__ W,
    const float* __restrict__ attn_l, const float* __restrict__ attn_r)
{
    __shared__ float As[2 * ATF];
    __shared__ float Bs[2 * BTF];
    const int tid  = threadIdx.x;
    const int warp = tid >> 5, lane = tid & 31;
    const int wr = warp >> 2, wc = warp & 3;
    const int gid = lane >> 2, tig = lane & 3;
    const int row0 = blockIdx.x * 128;

    const unsigned as_b = (unsigned)__cvta_generic_to_shared(As);
    const unsigned bs_b = (unsigned)__cvta_generic_to_shared(Bs);

    const int ac0 = tid, ac1 = tid + 256;
    const int ar0 = ac0 >> 2, ao0 = (ac0 & 3) * 4;
    const int ar1 = ac1 >> 2, ao1 = (ac1 & 3) * 4;
    const int g0 = row0 + ar0, g1 = row0 + ar1;
    const int av0 = (g0 < NN) ? 16 : 0, av1 = (g1 < NN) ? 16 : 0;
    const float* ap0 = x + (long)((g0 < NN) ? g0 : 0) * IN_DIM + ao0;
    const float* ap1 = x + (long)((g1 < NN) ? g1 : 0) * IN_DIM + ao1;
    const int br0 = ac0 >> 5, bo0 = (ac0 & 31) * 4;
    const int br1 = ac1 >> 5, bo1 = (ac1 & 31) * 4;
    const float* bp0 = W + br0 * HD + bo0;
    const float* bp1 = W + br1 * HD + bo1;

    auto load_tile = [&](int k0, int s) {
        unsigned ab = as_b + 4u * (s * ATF);
        unsigned bb = bs_b + 4u * (s * BTF);
        cp_async16(ab + 4u * (ar0 * SA2 + ao0), ap0 + k0, av0);
        cp_async16(ab + 4u * (ar1 * SA2 + ao1), ap1 + k0, av1);
        cp_async16(bb + 4u * (br0 * SB2 + bo0), bp0 + (long)k0 * HD, 16);
        cp_async16(bb + 4u * (br1 * SB2 + bo1), bp1 + (long)k0 * HD, 16);
        asm volatile("cp.async.commit_group;");
    };

    float4 c[4][4];
#pragma unroll
    for (int mt = 0; mt < 4; mt++)
#pragma unroll
        for (int nt = 0; nt < 4; nt++) c[mt][nt] = make_float4(0.f, 0.f, 0.f, 0.f);

    load_tile(0, 0);

    const int NT = IN_DIM / 16;    // 16 tiles
    for (int t = 0; t < NT; t++) {
        if (t + 1 < NT) {
            load_tile((t + 1) * 16, (t + 1) & 1);
            asm volatile("cp.async.wait_group 1;");
        } else {
            asm volatile("cp.async.wait_group 0;");
        }
        __syncthreads();

        const float* Af = As + (t & 1) * ATF;
        const float* Bf = Bs + (t & 1) * BTF;
#pragma unroll
        for (int kk = 0; kk < 2; kk++) {
            unsigned a[4][4], b[4][2];
            const int kb = kk * 8 + tig;
#pragma unroll
            for (int mt = 0; mt < 4; mt++) {
                int row = wr * 64 + mt * 16 + gid;
                a[mt][0] = f2tf32(Af[row * SA2 + kb]);
                a[mt][1] = f2tf32(Af[(row + 8) * SA2 + kb]);
                a[mt][2] = f2tf32(Af[row * SA2 + kb + 4]);
                a[mt][3] = f2tf32(Af[(row + 8) * SA2 + kb + 4]);
            }
#pragma unroll
            for (int nt = 0; nt < 4; nt++) {
                int col = wc * 32 + nt * 8 + gid;
                b[nt][0] = f2tf32(Bf[kb * SB2 + col]);
                b[nt][1] = f2tf32(Bf[(kb + 4) * SB2 + col]);
            }
#pragma unroll
            for (int mt = 0; mt < 4; mt++)
#pragma unroll
                for (int nt = 0; nt < 4; nt++)
                    mma_tf32(c[mt][nt], a[mt], b[nt][0], b[nt][1]);
        }
        __syncthreads();   // stage (t&1) free for tile t+2's loads
    }

    // ---- epilogue: store h (fp16), reduce el/er fp32 (warp-col wc == head) --
    const int head = wc;
    float al[4][2], arr[4][2];
#pragma unroll
    for (int nt = 0; nt < 4; nt++) {
        int col = wc * 32 + nt * 8 + 2 * tig;
        al[nt][0] = attn_l[col];     al[nt][1] = attn_l[col + 1];
        arr[nt][0] = attn_r[col];    arr[nt][1] = attn_r[col + 1];
    }

#pragma unroll
    for (int mt = 0; mt < 4; mt++) {
        int r0 = row0 + wr * 64 + mt * 16 + gid;     // and r0+8
        float pl0 = 0.f, pr0 = 0.f, pl1 = 0.f, pr1 = 0.f;
#pragma unroll
        for (int nt = 0; nt < 4; nt++) {
            float4 v = c[mt][nt];
            pl0 = fmaf(v.x, al[nt][0], fmaf(v.y, al[nt][1], pl0));
            pr0 = fmaf(v.x, arr[nt][0], fmaf(v.y, arr[nt][1], pr0));
            pl1 = fmaf(v.z, al[nt][0], fmaf(v.w, al[nt][1], pl1));
            pr1 = fmaf(v.z, arr[nt][0], fmaf(v.w, arr[nt][1], pr1));
        }
#pragma unroll
        for (int o = 1; o <= 2; o <<= 1) {
            pl0 += __shfl_xor_sync(0xffffffffu, pl0, o);
            pr0 += __shfl_xor_sync(0xffffffffu, pr0, o);
            pl1 += __shfl_xor_sync(0xffffffffu, pl1, o);
            pr1 += __shfl_xor_sync(0xffffffffu, pr1, o);
        }
        if (tig == 0) {
            if (r0 < NN)     { g_el[r0 * 4 + head] = pl0;       g_er[r0 * 4 + head] = pr0; }
            if (r0 + 8 < NN) { g_el[(r0 + 8) * 4 + head] = pl1; g_er[(r0 + 8) * 4 + head] = pr1; }
        }
#pragma unroll
        for (int nt = 0; nt < 4; nt++) {
            int col = wc * 32 + nt * 8 + 2 * tig;
            float4 v = c[mt][nt];
            if (r0 < NN)
                *(__half2*)&g_hh[r0 * HD + col]       = __floats2half2_rn(v.x, v.y);
            if (r0 + 8 < NN)
                *(__half2*)&g_hh[(r0 + 8) * HD + col] = __floats2half2_rn(v.z, v.w);
        }
    }
}

// ---------------- fused softmax + aggregation: one warp per dst node ---------
// R14-proven: independent warp retirement, 2-edge pipeline, fp16 gather.
__global__ void __launch_bounds__(256) agg_kernel() {
    int gwarp = (blockIdx.x * 256 + threadIdx.x) >> 5;
    int l = threadIdx.x & 31;
    if (gwarp >= NN) return;
    const int d = gwarp;
    const int beg = (int)g_off[d], end = (int)g_off[d + 1];

    const float4 er4 = ((const float4*)g_er)[d];
    const int hh = l >> 3;                 // 8 lanes per head
    const float erc = sel4(er4, hh);

    float4 acc = make_float4(0.f, 0.f, 0.f, 0.f);
    float sumex = 0.f;
    const uint2* hmat = (const uint2*)g_hh;   // row = 32 uint2 (128 halves)

    int i = beg;
    for (; i + 1 < end; i += 2) {
        int s0 = __ldg(&g_esrc[i]);
        int s1 = __ldg(&g_esrc[i + 1]);
        float4 el0 = ((const float4*)g_el)[s0];
        float4 el1 = ((const float4*)g_el)[s1];
        uint2 u0 = hmat[s0 * 32 + l];
        uint2 u1 = hmat[s1 * 32 + l];

        float e0 = sel4(el0, hh) + erc;
        e0 = e0 > 0.f ? e0 : NEG_SLOPE * e0;
        float ex0 = __expf(e0);
        float e1 = sel4(el1, hh) + erc;
        e1 = e1 > 0.f ? e1 : NEG_SLOPE * e1;
        float ex1 = __expf(e1);
        sumex += ex0 + ex1;

        float2 a01 = __half22float2(*(__half2*)&u0.x);
        float2 a23 = __half22float2(*(__half2*)&u0.y);
        float2 b01 = __half22float2(*(__half2*)&u1.x);
        float2 b23 = __half22float2(*(__half2*)&u1.y);
        acc.x = fmaf(ex0, a01.x, fmaf(ex1, b01.x, acc.x));
        acc.y = fmaf(ex0, a01.y, fmaf(ex1, b01.y, acc.y));
        acc.z = fmaf(ex0, a23.x, fmaf(ex1, b23.x, acc.z));
        acc.w = fmaf(ex0, a23.y, fmaf(ex1, b23.y, acc.w));
    }
    if (i < end) {
        int s = __ldg(&g_esrc[i]);
        float4 el4 = ((const float4*)g_el)[s];
        uint2 u0 = hmat[s * 32 + l];
        float e = sel4(el4, hh) + erc;
        e = e > 0.f ? e : NEG_SLOPE * e;
        float ex = __expf(e);
        sumex += ex;
        float2 a01 = __half22float2(*(__half2*)&u0.x);
        float2 a23 = __half22float2(*(__half2*)&u0.y);
        acc.x = fmaf(ex, a01.x, acc.x);
        acc.y = fmaf(ex, a01.y, acc.y);
        acc.z = fmaf(ex, a23.x, acc.z);
        acc.w = fmaf(ex, a23.y, acc.w);
    }
    float inv = (sumex > 0.f) ? 1.f / sumex : 0.f;
    float4 o;
    o.x = acc.x * inv; o.y = acc.y * inv; o.z = acc.z * inv; o.w = acc.w * inv;
    ((float4*)g_rst)[d * 32 + l] = o;
}

// ---------------- BN stats (vectorized: warp-per-row float4) -----------------
// 512 blocks x 8 warps; warp w reads rows blockIdx*8+w, +4096, ... Lane l
// accumulates channels 4l..4l+3 in registers; 8-warp smem tree; 131k atomics
// total on 256 addresses (proven-cheap scale).
__global__ void __launch_bounds__(256) bn_stats_kernel() {
    const int warp = threadIdx.x >> 5, l = threadIdx.x & 31;
    float4 s  = make_float4(0.f, 0.f, 0.f, 0.f);
    float4 s2 = make_float4(0.f, 0.f, 0.f, 0.f);
    for (int r = blockIdx.x * 8 + warp; r < NN; r += 512 * 8) {
        float4 v = ((const float4*)g_rst)[r * 32 + l];
        s.x += v.x; s.y += v.y; s.z += v.z; s.w += v.w;
        s2.x = fmaf(v.x, v.x, s2.x); s2.y = fmaf(v.y, v.y, s2.y);
        s2.z = fmaf(v.z, v.z, s2.z); s2.w = fmaf(v.w, v.w, s2.w);
    }
    __shared__ float4 ssum[8][32], ssq[8][32];
    ssum[warp][l] = s;  ssq[warp][l] = s2;
    __syncthreads();
    if (warp == 0) {
        float4 a = ssum[0][l], a2 = ssq[0][l];
#pragma unroll
        for (int w = 1; w < 8; w++) {
            float4 b = ssum[w][l], b2 = ssq[w][l];
            a.x += b.x; a.y += b.y; a.z += b.z; a.w += b.w;
            a2.x += b2.x; a2.y += b2.y; a2.z += b2.z; a2.w += b2.w;
        }
        atomicAdd(&g_sums[4 * l + 0], a.x);
        atomicAdd(&g_sums[4 * l + 1], a.y);
        atomicAdd(&g_sums[4 * l + 2], a.z);
        atomicAdd(&g_sums[4 * l + 3], a.w);
        atomicAdd(&g_sumsq[4 * l + 0], a2.x);
        atomicAdd(&g_sumsq[4 * l + 1], a2.y);
        atomicAdd(&g_sumsq[4 * l + 2], a2.z);
        atomicAdd(&g_sumsq[4 * l + 3], a2.w);
    }
}

// ---------------- BN normalize + ReLU + next-replay cleanup ------------------
__global__ void bn_apply_kernel(const float* __restrict__ gamma,
                                const float* __restrict__ beta,
                                float* __restrict__ out)
{
    int i = blockIdx.x * blockDim.x + threadIdx.x;   // NN*HD/4 threads
    int c0 = (i * 4) & (HD - 1);
    const float inv_n = 1.f / (float)NN;
    float4 v = ((const float4*)g_rst)[i];
    float4 o;
#pragma unroll
    for (int j = 0; j < 4; j++) {
        int c = c0 + j;
        float mean = g_sums[c] * inv_n;
        float var  = g_sumsq[c] * inv_n - mean * mean;
        float vv = (j == 0) ? v.x : (j == 1) ? v.y : (j == 2) ? v.z : v.w;
        float y = gamma[c] * (vv - mean) * rsqrtf(var + BN_EPS) + beta[c];
        y = y > 0.f ? y : 0.f;
        if (j == 0) o.x = y; else if (j == 1) o.y = y;
        else if (j == 2) o.z = y; else o.w = y;
    }
    ((float4*)out)[i] = o;
    // reset g_cnt for the next replay (g_cnt's last read was launch 2)
    if (i < NN) g_cnt[i] = 0u;
}

// ---------------- launch -----------------------------------------------------
// 8 launches. scatter_kernel at profiled slot #4.
extern "C" void kernel_launch(void* const* d_in, const int* in_sizes, int n_in,
                              void* d_out, int out_size)
{
    const float* x      = (const float*)d_in[0];
    const int*   src    = (const int*)d_in[1];
    const int*   dst    = (const int*)d_in[2];
    const float* W      = (const float*)d_in[3];
    const float* attn_l = (const float*)d_in[4];
    const float* attn_r = (const float*)d_in[5];
    // d_in[6] = bias: constant per-channel shift, cancels inside batch-norm
    const float* gamma  = (const float*)d_in[7];
    const float* beta   = (const float*)d_in[8];
    float* out = (float*)d_out;

    hist_kernel<<<(EE + 255) / 256, 256>>>(dst);
    scan_block_kernel<<<NB, 256>>>();
    scan_fused_kernel<<<NB, 256>>>();
    scatter_kernel<<<(EE + 255) / 256, 256>>>(src, dst);   // profiled
    gemm_kernel<<<(NN + 127) / 128, 256>>>(x, W, attn_l, attn_r);
    agg_kernel<<<(NN * 32 + 255) / 256, 256>>>();
    bn_stats_kernel<<<512, 256>>>();
    bn_apply_kernel<<<(NN * HD / 4 + 255) / 256, 256>>>(gamma, beta, out);
}